// round 1
// baseline (speedup 1.0000x reference)
#include <cuda_runtime.h>
#include <cstdint>

// ---------------------------------------------------------------------------
// GCNWithSubgraphs: sub GCNConv -> relu -> subgraph mean pool -> inject into
// global graph -> global GCNConv -> relu -> global mean -> FC.
// H = 256 throughout.
// ---------------------------------------------------------------------------

#define H 256
#define MAX_NSUB  32768
#define MAX_NGLOB 65536
#define MAX_S     1024

// Scratch (device globals; no allocation allowed)
__device__ float g_h_sub[MAX_NSUB * H];     // x_sub @ W_sub
__device__ float g_out_sub[MAX_NSUB * H];   // conv accumulator (sub)
__device__ float g_gx[MAX_NGLOB * H];       // injected global features
__device__ float g_h_glob[MAX_NGLOB * H];   // gx @ W_glob
__device__ float g_out_glob[MAX_NGLOB * H]; // conv accumulator (glob)
__device__ float g_deg_sub[MAX_NSUB];
__device__ float g_deg_glob[MAX_NGLOB];
__device__ float g_pool_sum[MAX_S * H];
__device__ float g_pool_cnt[MAX_S];
__device__ float g_gemb[H];

// ---------------------------------------------------------------------------
// vectorized fp32 reduction (sm_90+): 4 floats per atomic op
// ---------------------------------------------------------------------------
__device__ __forceinline__ void red_add_v4(float* a, float4 v) {
    asm volatile("red.global.add.v4.f32 [%0], {%1,%2,%3,%4};"
                 :: "l"(a), "f"(v.x), "f"(v.y), "f"(v.z), "f"(v.w)
                 : "memory");
}

// ---------------------------------------------------------------------------
// init: degrees = 1 (self loop), pool sums/cnt = 0, gemb = 0
// ---------------------------------------------------------------------------
__global__ void k_init(int n_sub, int n_glob, int s) {
    int i = blockIdx.x * blockDim.x + threadIdx.x;
    if (i < n_sub)  g_deg_sub[i]  = 1.0f;
    if (i < n_glob) g_deg_glob[i] = 1.0f;
    if (i < s * H)  g_pool_sum[i] = 0.0f;
    if (i < s)      g_pool_cnt[i] = 0.0f;
    if (i < H)      g_gemb[i]     = 0.0f;
}

__global__ void k_deg(const int* __restrict__ col, int E, float* deg) {
    int i = blockIdx.x * blockDim.x + threadIdx.x;
    if (i < E) atomicAdd(&deg[col[i]], 1.0f);
}

// ---------------------------------------------------------------------------
// SGEMM: C[M,256] = A[M,256] @ B[256,256], row-major. M % 128 == 0.
// 128x128 block tile, BK=8, 8x8 per thread, 256 threads.
// ---------------------------------------------------------------------------
__global__ __launch_bounds__(256) void k_sgemm(const float* __restrict__ A,
                                               const float* __restrict__ B,
                                               float* __restrict__ C, int M) {
    const int K = H, N = H;
    __shared__ float As[8][128];
    __shared__ float Bs[8][128];

    int bc = blockIdx.x;          // 0..1 (N/128)
    int br = blockIdx.y;          // M/128
    int tid = threadIdx.x;
    int tr = tid / 16, tc = tid % 16;

    int arow = tid >> 1;          // 0..127
    int acol = (tid & 1) * 4;     // 0 or 4
    int brow = tid >> 5;          // 0..7
    int bcol = (tid & 31) * 4;    // 0..124

    const float* Ab = A + (size_t)br * 128 * K;
    const float* Bb = B + bc * 128;

    float acc[8][8];
    #pragma unroll
    for (int i = 0; i < 8; i++)
        #pragma unroll
        for (int j = 0; j < 8; j++) acc[i][j] = 0.0f;

    for (int k0 = 0; k0 < K; k0 += 8) {
        float4 a4 = *(const float4*)(Ab + arow * K + k0 + acol);
        As[acol + 0][arow] = a4.x;
        As[acol + 1][arow] = a4.y;
        As[acol + 2][arow] = a4.z;
        As[acol + 3][arow] = a4.w;
        float4 b4 = *(const float4*)(Bb + (k0 + brow) * N + bcol);
        *(float4*)&Bs[brow][bcol] = b4;
        __syncthreads();

        #pragma unroll
        for (int kk = 0; kk < 8; kk++) {
            float ar[8], bcr[8];
            #pragma unroll
            for (int i = 0; i < 8; i++) ar[i] = As[kk][tr * 8 + i];
            #pragma unroll
            for (int j = 0; j < 8; j++) bcr[j] = Bs[kk][tc * 8 + j];
            #pragma unroll
            for (int i = 0; i < 8; i++)
                #pragma unroll
                for (int j = 0; j < 8; j++) acc[i][j] += ar[i] * bcr[j];
        }
        __syncthreads();
    }

    float* Cb = C + (size_t)br * 128 * N + bc * 128;
    #pragma unroll
    for (int i = 0; i < 8; i++)
        #pragma unroll
        for (int j = 0; j < 8; j += 4) {
            float4 v = make_float4(acc[i][j], acc[i][j+1], acc[i][j+2], acc[i][j+3]);
            *(float4*)(Cb + (tr * 8 + i) * N + tc * 8 + j) = v;
        }
}

// ---------------------------------------------------------------------------
// out[n,f] = h[n,f] / deg[n] + bias[f]   (self-loop term initializes accum)
// ---------------------------------------------------------------------------
__global__ void k_selfinit(const float* __restrict__ h, const float* __restrict__ deg,
                           const float* __restrict__ bias, float* __restrict__ out, int n) {
    int i = blockIdx.x * blockDim.x + threadIdx.x;
    if (i < n * H) {
        int node = i >> 8;
        out[i] = h[i] * (1.0f / deg[node]) + bias[i & (H - 1)];
    }
}

// ---------------------------------------------------------------------------
// edge scatter: out[col] += h[row] * rsqrt(deg[row]*deg[col]); 1 warp / edge
// ---------------------------------------------------------------------------
__global__ __launch_bounds__(256) void k_scatter(const float* __restrict__ h,
                                                 float* __restrict__ out,
                                                 const int* __restrict__ rows,
                                                 const int* __restrict__ cols,
                                                 const float* __restrict__ deg, int E) {
    int warp = (blockIdx.x * blockDim.x + threadIdx.x) >> 5;
    int lane = threadIdx.x & 31;
    if (warp >= E) return;
    int r = rows[warp];
    int c = cols[warp];
    float norm = rsqrtf(deg[r] * deg[c]);
    const float4* hr = (const float4*)(h + (size_t)r * H);
    float* oc = out + (size_t)c * H;
    #pragma unroll
    for (int j = 0; j < 2; j++) {
        int f4 = lane + j * 32;            // float4 index 0..63
        float4 v = __ldg(hr + f4);
        v.x *= norm; v.y *= norm; v.z *= norm; v.w *= norm;
        red_add_v4(oc + f4 * 4, v);
    }
}

// relu + subgraph pooled sums
__global__ void k_pool(const float* __restrict__ out_sub, const int* __restrict__ batch, int n) {
    int i = blockIdx.x * blockDim.x + threadIdx.x;
    if (i < n * H) {
        int node = i >> 8;
        int s = batch[node];
        float v = out_sub[i];
        v = v > 0.0f ? v : 0.0f;
        atomicAdd(&g_pool_sum[s * H + (i & (H - 1))], v);
    }
}

__global__ void k_cnt(const int* __restrict__ batch, int n) {
    int i = blockIdx.x * blockDim.x + threadIdx.x;
    if (i < n) atomicAdd(&g_pool_cnt[batch[i]], 1.0f);
}

// gx = x_glob (float4 copy)
__global__ void k_copy(const float4* __restrict__ src, float4* __restrict__ dst, int n4) {
    int i = blockIdx.x * blockDim.x + threadIdx.x;
    if (i < n4) dst[i] = src[i];
}

// gx[sub_index[s]] += pool_sum[s] / max(cnt[s],1)
__global__ void k_inject(const int* __restrict__ sub_index, int s) {
    int i = blockIdx.x * blockDim.x + threadIdx.x;
    if (i < s * H) {
        int g = i >> 8;
        int node = sub_index[g];
        float cnt = g_pool_cnt[g];
        float m = g_pool_sum[i] / fmaxf(cnt, 1.0f);
        atomicAdd(&g_gx[(size_t)node * H + (i & (H - 1))], m);
    }
}

// gemb[f] += sum over block's rows of relu(out_glob[n,f])
__global__ __launch_bounds__(256) void k_reduce(const float* __restrict__ out_glob, int n) {
    int f = threadIdx.x;                 // 0..255
    int r0 = blockIdx.x * 256;
    int r1 = min(r0 + 256, n);
    float s = 0.0f;
    for (int r = r0; r < r1; r++) {
        float v = out_glob[(size_t)r * H + f];
        s += v > 0.0f ? v : 0.0f;
    }
    atomicAdd(&g_gemb[f], s);
}

// out[j] = (gemb/n_glob) . fc_W[j,:] + fc_b[j]
__global__ void k_final(const float* __restrict__ fc_W, const float* __restrict__ fc_b,
                        float* __restrict__ out, float inv_n) {
    __shared__ float ge[H];
    int t = threadIdx.x;
    ge[t] = g_gemb[t] * inv_n;
    __syncthreads();
    float s = 0.0f;
    #pragma unroll 8
    for (int f = 0; f < H; f++) s += ge[f] * fc_W[t * H + f];
    out[t] = s + fc_b[t];
}

// ---------------------------------------------------------------------------
extern "C" void kernel_launch(void* const* d_in, const int* in_sizes, int n_in,
                              void* d_out, int out_size) {
    const float* x_sub      = (const float*)d_in[0];
    const int*   ei_sub     = (const int*)  d_in[1];
    const int*   batch_sub  = (const int*)  d_in[2];
    const int*   sub_index  = (const int*)  d_in[3];
    const float* x_glob     = (const float*)d_in[4];
    const int*   ei_glob    = (const int*)  d_in[5];
    // d_in[6] = batch_glob (all zeros -> single segment)
    const float* W_sub      = (const float*)d_in[7];
    const float* b_sub      = (const float*)d_in[8];
    const float* W_glob     = (const float*)d_in[9];
    const float* b_glob     = (const float*)d_in[10];
    const float* fc_W       = (const float*)d_in[11];
    const float* fc_b       = (const float*)d_in[12];
    float* out = (float*)d_out;

    const int n_sub  = in_sizes[0] / H;     // 32768
    const int E_sub  = in_sizes[1] / 2;     // 262144
    const int S      = in_sizes[3];         // 1024
    const int n_glob = in_sizes[4] / H;     // 65536
    const int E_glob = in_sizes[5] / 2;     // 1048576

    const int* rows_sub  = ei_sub;
    const int* cols_sub  = ei_sub + E_sub;
    const int* rows_glob = ei_glob;
    const int* cols_glob = ei_glob + E_glob;

    float* h_sub    = nullptr; cudaGetSymbolAddress((void**)&h_sub,    g_h_sub);
    float* out_sub  = nullptr; cudaGetSymbolAddress((void**)&out_sub,  g_out_sub);
    float* gx       = nullptr; cudaGetSymbolAddress((void**)&gx,       g_gx);
    float* h_glob   = nullptr; cudaGetSymbolAddress((void**)&h_glob,   g_h_glob);
    float* out_glob = nullptr; cudaGetSymbolAddress((void**)&out_glob, g_out_glob);
    float* deg_sub  = nullptr; cudaGetSymbolAddress((void**)&deg_sub,  g_deg_sub);
    float* deg_glob = nullptr; cudaGetSymbolAddress((void**)&deg_glob, g_deg_glob);

    const int T = 256;

    // init + degrees
    {
        int span = S * H;                 // 262144 dominates
        if (n_glob > span) span = n_glob;
        k_init<<<(span + T - 1) / T, T>>>(n_sub, n_glob, S);
    }
    k_deg<<<(E_sub  + T - 1) / T, T>>>(cols_sub,  E_sub,  deg_sub);
    k_deg<<<(E_glob + T - 1) / T, T>>>(cols_glob, E_glob, deg_glob);

    // ---- sub conv ----
    k_sgemm<<<dim3(2, n_sub / 128), 256>>>(x_sub, W_sub, h_sub, n_sub);
    k_selfinit<<<(n_sub * H + T - 1) / T, T>>>(h_sub, deg_sub, b_sub, out_sub, n_sub);
    k_scatter<<<(E_sub * 32 + T - 1) / T, T>>>(h_sub, out_sub, rows_sub, cols_sub, deg_sub, E_sub);

    // relu + pool
    k_pool<<<(n_sub * H + T - 1) / T, T>>>(out_sub, batch_sub, n_sub);
    k_cnt<<<(n_sub + T - 1) / T, T>>>(batch_sub, n_sub);

    // ---- inject into global ----
    k_copy<<<(n_glob * H / 4 + T - 1) / T, T>>>((const float4*)x_glob, (float4*)gx, n_glob * H / 4);
    k_inject<<<(S * H + T - 1) / T, T>>>(sub_index, S);

    // ---- global conv ----
    k_sgemm<<<dim3(2, n_glob / 128), 256>>>(gx, W_glob, h_glob, n_glob);
    k_selfinit<<<(n_glob * H + T - 1) / T, T>>>(h_glob, deg_glob, b_glob, out_glob, n_glob);
    k_scatter<<<(E_glob * 32 + T - 1) / T, T>>>(h_glob, out_glob, rows_glob, cols_glob, deg_glob, E_glob);

    // ---- relu + global mean + FC ----
    k_reduce<<<(n_glob + 255) / 256, 256>>>(out_glob, n_glob);
    k_final<<<1, H>>>(fc_W, fc_b, out, 1.0f / (float)n_glob);
}

// round 2
// speedup vs baseline: 1.3027x; 1.3027x over previous
#include <cuda_runtime.h>
#include <cstdint>

// ---------------------------------------------------------------------------
// GCNWithSubgraphs, gather-based:
//   counting-sort edges by target -> warp-per-node gather (register accum)
//   -> fused bias+relu+pool / bias+relu+global-reduce epilogues.
// H = 256 throughout.
// ---------------------------------------------------------------------------

#define H 256
#define MAX_NSUB  32768
#define MAX_NGLOB 65536
#define MAX_S     1024
#define MAX_ESUB  262144
#define MAX_EGLOB 1048576

__device__ float g_h_sub[MAX_NSUB * H];     // x_sub @ W_sub
__device__ float g_h_glob[MAX_NGLOB * H];   // x_glob @ W_glob (+ injection)
__device__ float g_pool_sum[MAX_S * H];
__device__ float g_pool_mean[MAX_S * H];
__device__ float g_pooledW[MAX_S * H];      // pool_mean @ W_glob
__device__ float g_pool_cnt[MAX_S];
__device__ float g_gemb[H];

__device__ int   g_cnt_sub[MAX_NSUB];
__device__ int   g_off_sub[MAX_NSUB + 1];
__device__ int   g_cur_sub[MAX_NSUB];
__device__ float g_dinv_sub[MAX_NSUB];
__device__ int   g_srcs_sub[MAX_ESUB];

__device__ int   g_cnt_glob[MAX_NGLOB];
__device__ int   g_off_glob[MAX_NGLOB + 1];
__device__ int   g_cur_glob[MAX_NGLOB];
__device__ float g_dinv_glob[MAX_NGLOB];
__device__ int   g_srcs_glob[MAX_EGLOB];

__device__ int   g_bsum_sub[256];
__device__ int   g_bsum_glob[256];

// vectorized fp32 reduction (sm_90+)
__device__ __forceinline__ void red_add_v4(float* a, float4 v) {
    asm volatile("red.global.add.v4.f32 [%0], {%1,%2,%3,%4};"
                 :: "l"(a), "f"(v.x), "f"(v.y), "f"(v.z), "f"(v.w)
                 : "memory");
}

__device__ __forceinline__ float4 f4_fma(float4 a, float s, float4 acc) {
    acc.x = fmaf(a.x, s, acc.x); acc.y = fmaf(a.y, s, acc.y);
    acc.z = fmaf(a.z, s, acc.z); acc.w = fmaf(a.w, s, acc.w);
    return acc;
}
__device__ __forceinline__ float4 f4_relu_addb(float4 a, float4 b) {
    float4 r;
    r.x = fmaxf(a.x + b.x, 0.0f); r.y = fmaxf(a.y + b.y, 0.0f);
    r.z = fmaxf(a.z + b.z, 0.0f); r.w = fmaxf(a.w + b.w, 0.0f);
    return r;
}

// ---------------------------------------------------------------------------
// init: zero counts / pool / gemb
// ---------------------------------------------------------------------------
__global__ void k_init(int n_sub, int n_glob, int s) {
    int i = blockIdx.x * blockDim.x + threadIdx.x;
    if (i < n_sub)  g_cnt_sub[i]  = 0;
    if (i < n_glob) g_cnt_glob[i] = 0;
    if (i < s * H)  g_pool_sum[i] = 0.0f;
    if (i < s)      g_pool_cnt[i] = 0.0f;
    if (i < H)      g_gemb[i]     = 0.0f;
}

__global__ void k_count(const int* __restrict__ col, int E, int* __restrict__ cnt) {
    int i = blockIdx.x * blockDim.x + threadIdx.x;
    if (i < E) atomicAdd(&cnt[col[i]], 1);
}

// per-256-chunk block sums
__global__ void k_blocksum(const int* __restrict__ cnt, int* __restrict__ bsum) {
    __shared__ int sh[256];
    int t = threadIdx.x;
    sh[t] = cnt[blockIdx.x * 256 + t];
    __syncthreads();
    #pragma unroll
    for (int s = 128; s > 0; s >>= 1) {
        if (t < s) sh[t] += sh[t + s];
        __syncthreads();
    }
    if (t == 0) bsum[blockIdx.x] = sh[0];
}

// exclusive scan of block sums (single block, NB <= 256)
__global__ void k_scan_bsum(int* __restrict__ bsum, int NB) {
    __shared__ int sh[256];
    int t = threadIdx.x;
    sh[t] = (t < NB) ? bsum[t] : 0;
    __syncthreads();
    #pragma unroll
    for (int d = 1; d < 256; d <<= 1) {
        int v = (t >= d) ? sh[t - d] : 0;
        __syncthreads();
        sh[t] += v;
        __syncthreads();
    }
    int ex = (t == 0) ? 0 : sh[t - 1];
    if (t < NB) bsum[t] = ex;
}

// per-chunk exclusive scan + base -> off/cur, plus dinv = rsqrt(cnt+1)
__global__ void k_scan_chunks(const int* __restrict__ cnt, const int* __restrict__ bsum,
                              int* __restrict__ off, int* __restrict__ cur,
                              float* __restrict__ dinv, int N) {
    __shared__ int sh[256];
    int t = threadIdx.x;
    int i = blockIdx.x * 256 + t;
    int c = cnt[i];
    sh[t] = c;
    __syncthreads();
    #pragma unroll
    for (int d = 1; d < 256; d <<= 1) {
        int v = (t >= d) ? sh[t - d] : 0;
        __syncthreads();
        sh[t] += v;
        __syncthreads();
    }
    int excl = sh[t] - c + bsum[blockIdx.x];
    off[i] = excl;
    cur[i] = excl;
    dinv[i] = rsqrtf((float)(c + 1));     // +1 self loop
    if (i == N - 1) off[N] = excl + c;
}

__global__ void k_bucket(const int* __restrict__ rows, const int* __restrict__ cols,
                         int* __restrict__ cur, int* __restrict__ srcs, int E) {
    int e = blockIdx.x * blockDim.x + threadIdx.x;
    if (e < E) {
        int c = cols[e];
        int p = atomicAdd(&cur[c], 1);
        srcs[p] = rows[e];
    }
}

// ---------------------------------------------------------------------------
// SGEMM: C[M,256] = A[M,256] @ B[256,256], row-major. M % 128 == 0.
// ---------------------------------------------------------------------------
__global__ __launch_bounds__(256) void k_sgemm(const float* __restrict__ A,
                                               const float* __restrict__ B,
                                               float* __restrict__ C, int M) {
    const int K = H, N = H;
    __shared__ float As[8][128];
    __shared__ float Bs[8][128];

    int bc = blockIdx.x;
    int br = blockIdx.y;
    int tid = threadIdx.x;
    int tr = tid / 16, tc = tid % 16;

    int arow = tid >> 1;
    int acol = (tid & 1) * 4;
    int brow = tid >> 5;
    int bcol = (tid & 31) * 4;

    const float* Ab = A + (size_t)br * 128 * K;
    const float* Bb = B + bc * 128;

    float acc[8][8];
    #pragma unroll
    for (int i = 0; i < 8; i++)
        #pragma unroll
        for (int j = 0; j < 8; j++) acc[i][j] = 0.0f;

    for (int k0 = 0; k0 < K; k0 += 8) {
        float4 a4 = *(const float4*)(Ab + arow * K + k0 + acol);
        As[acol + 0][arow] = a4.x;
        As[acol + 1][arow] = a4.y;
        As[acol + 2][arow] = a4.z;
        As[acol + 3][arow] = a4.w;
        float4 b4 = *(const float4*)(Bb + (k0 + brow) * N + bcol);
        *(float4*)&Bs[brow][bcol] = b4;
        __syncthreads();

        #pragma unroll
        for (int kk = 0; kk < 8; kk++) {
            float ar[8], bcr[8];
            #pragma unroll
            for (int i = 0; i < 8; i++) ar[i] = As[kk][tr * 8 + i];
            #pragma unroll
            for (int j = 0; j < 8; j++) bcr[j] = Bs[kk][tc * 8 + j];
            #pragma unroll
            for (int i = 0; i < 8; i++)
                #pragma unroll
                for (int j = 0; j < 8; j++) acc[i][j] += ar[i] * bcr[j];
        }
        __syncthreads();
    }

    float* Cb = C + (size_t)br * 128 * N + bc * 128;
    #pragma unroll
    for (int i = 0; i < 8; i++)
        #pragma unroll
        for (int j = 0; j < 8; j += 4) {
            float4 v = make_float4(acc[i][j], acc[i][j+1], acc[i][j+2], acc[i][j+3]);
            *(float4*)(Cb + (tr * 8 + i) * N + tc * 8 + j) = v;
        }
}

// ---------------------------------------------------------------------------
// gather core: warp per node; lane owns channels [4*lane..+3] and [128+4*lane..+3]
// ---------------------------------------------------------------------------
__device__ __forceinline__ void gather_node(const float4* __restrict__ hp,
                                            const int* __restrict__ off,
                                            const int* __restrict__ srcs,
                                            const float* __restrict__ dinv,
                                            int n, int lane,
                                            float4& a0, float4& a1) {
    int base = off[n];
    int end  = off[n + 1];
    float di = dinv[n];
    float sn = di * di;                     // self-loop norm = 1/deg
    const float4* hn = hp + (size_t)n * 64;
    a0 = hn[lane];      a1 = hn[lane + 32];
    a0.x *= sn; a0.y *= sn; a0.z *= sn; a0.w *= sn;
    a1.x *= sn; a1.y *= sn; a1.z *= sn; a1.w *= sn;

    int e = base;
    int r = (e < end) ? __ldg(&srcs[e]) : 0;
    for (; e < end; e++) {
        int rn = (e + 1 < end) ? __ldg(&srcs[e + 1]) : 0;
        float nm = di * __ldg(&dinv[r]);
        const float4* hr = hp + (size_t)r * 64;
        float4 v0 = __ldg(hr + lane);
        float4 v1 = __ldg(hr + lane + 32);
        a0 = f4_fma(v0, nm, a0);
        a1 = f4_fma(v1, nm, a1);
        r = rn;
    }
}

// sub: + bias, relu, pool-scatter (vector red into pool_sum)
__global__ __launch_bounds__(256) void k_gather_sub(const float* __restrict__ h,
                                                    const float* __restrict__ bias,
                                                    const int* __restrict__ batch, int N) {
    int warp = (blockIdx.x * blockDim.x + threadIdx.x) >> 5;
    int lane = threadIdx.x & 31;
    if (warp >= N) return;
    float4 a0, a1;
    gather_node((const float4*)h, g_off_sub, g_srcs_sub, g_dinv_sub, warp, lane, a0, a1);
    const float4* b4 = (const float4*)bias;
    a0 = f4_relu_addb(a0, __ldg(b4 + lane));
    a1 = f4_relu_addb(a1, __ldg(b4 + lane + 32));
    int s = batch[warp];
    float* ps = g_pool_sum + (size_t)s * H;
    red_add_v4(ps + 4 * lane, a0);
    red_add_v4(ps + 4 * (lane + 32), a1);
}

// glob: + bias, relu, block-shared reduce -> one global atomic per channel/block
__global__ __launch_bounds__(512) void k_gather_glob(const float* __restrict__ h,
                                                     const float* __restrict__ bias, int N) {
    __shared__ float sh[H];
    int t = threadIdx.x;
    if (t < H) sh[t] = 0.0f;
    __syncthreads();

    int warp = (blockIdx.x * blockDim.x + t) >> 5;
    int lane = t & 31;
    if (warp < N) {
        float4 a0, a1;
        gather_node((const float4*)h, g_off_glob, g_srcs_glob, g_dinv_glob, warp, lane, a0, a1);
        const float4* b4 = (const float4*)bias;
        a0 = f4_relu_addb(a0, __ldg(b4 + lane));
        a1 = f4_relu_addb(a1, __ldg(b4 + lane + 32));
        int c0 = 4 * lane, c1 = 4 * (lane + 32);
        atomicAdd(&sh[c0 + 0], a0.x); atomicAdd(&sh[c0 + 1], a0.y);
        atomicAdd(&sh[c0 + 2], a0.z); atomicAdd(&sh[c0 + 3], a0.w);
        atomicAdd(&sh[c1 + 0], a1.x); atomicAdd(&sh[c1 + 1], a1.y);
        atomicAdd(&sh[c1 + 2], a1.z); atomicAdd(&sh[c1 + 3], a1.w);
    }
    __syncthreads();
    if (t < H) atomicAdd(&g_gemb[t], sh[t]);
}

// pool counts
__global__ void k_cnt(const int* __restrict__ batch, int n) {
    int i = blockIdx.x * blockDim.x + threadIdx.x;
    if (i < n) atomicAdd(&g_pool_cnt[batch[i]], 1.0f);
}

// mean = sum / max(cnt,1)
__global__ void k_poolmean(int s) {
    int i = blockIdx.x * blockDim.x + threadIdx.x;
    if (i < s * H) {
        float c = g_pool_cnt[i >> 8];
        g_pool_mean[i] = g_pool_sum[i] / fmaxf(c, 1.0f);
    }
}

// h_glob[sub_index[g]] += pooledW[g]   (vectorized)
__global__ void k_inject(const int* __restrict__ sub_index, int s) {
    int i = blockIdx.x * blockDim.x + threadIdx.x;     // float4 index
    if (i < s * 64) {
        int g  = i >> 6;
        int f4 = i & 63;
        int node = sub_index[g];
        float4 v = ((const float4*)g_pooledW)[i];
        red_add_v4(&g_h_glob[(size_t)node * H + 4 * f4], v);
    }
}

// out[j] = (gemb/n_glob) . fc_W[j,:] + fc_b[j]
__global__ void k_final(const float* __restrict__ fc_W, const float* __restrict__ fc_b,
                        float* __restrict__ out, float inv_n) {
    __shared__ float ge[H];
    int t = threadIdx.x;
    ge[t] = g_gemb[t] * inv_n;
    __syncthreads();
    float s = 0.0f;
    #pragma unroll 8
    for (int f = 0; f < H; f++) s += ge[f] * fc_W[t * H + f];
    out[t] = s + fc_b[t];
}

// ---------------------------------------------------------------------------
extern "C" void kernel_launch(void* const* d_in, const int* in_sizes, int n_in,
                              void* d_out, int out_size) {
    const float* x_sub      = (const float*)d_in[0];
    const int*   ei_sub     = (const int*)  d_in[1];
    const int*   batch_sub  = (const int*)  d_in[2];
    const int*   sub_index  = (const int*)  d_in[3];
    const float* x_glob     = (const float*)d_in[4];
    const int*   ei_glob    = (const int*)  d_in[5];
    const float* W_sub      = (const float*)d_in[7];
    const float* b_sub      = (const float*)d_in[8];
    const float* W_glob     = (const float*)d_in[9];
    const float* b_glob     = (const float*)d_in[10];
    const float* fc_W       = (const float*)d_in[11];
    const float* fc_b       = (const float*)d_in[12];
    float* out = (float*)d_out;

    const int n_sub  = in_sizes[0] / H;     // 32768
    const int E_sub  = in_sizes[1] / 2;     // 262144
    const int S      = in_sizes[3];         // 1024
    const int n_glob = in_sizes[4] / H;     // 65536
    const int E_glob = in_sizes[5] / 2;     // 1048576

    const int* rows_sub  = ei_sub;
    const int* cols_sub  = ei_sub + E_sub;
    const int* rows_glob = ei_glob;
    const int* cols_glob = ei_glob + E_glob;

    float* h_sub   ; cudaGetSymbolAddress((void**)&h_sub,    g_h_sub);
    float* h_glob  ; cudaGetSymbolAddress((void**)&h_glob,   g_h_glob);
    float* pmean   ; cudaGetSymbolAddress((void**)&pmean,    g_pool_mean);
    float* pooledW ; cudaGetSymbolAddress((void**)&pooledW,  g_pooledW);
    int* cnt_sub   ; cudaGetSymbolAddress((void**)&cnt_sub,  g_cnt_sub);
    int* cnt_glob  ; cudaGetSymbolAddress((void**)&cnt_glob, g_cnt_glob);
    int* off_sub   ; cudaGetSymbolAddress((void**)&off_sub,  g_off_sub);
    int* off_glob  ; cudaGetSymbolAddress((void**)&off_glob, g_off_glob);
    int* cur_sub   ; cudaGetSymbolAddress((void**)&cur_sub,  g_cur_sub);
    int* cur_glob  ; cudaGetSymbolAddress((void**)&cur_glob, g_cur_glob);
    float* dinv_sub ; cudaGetSymbolAddress((void**)&dinv_sub,  g_dinv_sub);
    float* dinv_glob; cudaGetSymbolAddress((void**)&dinv_glob, g_dinv_glob);
    int* srcs_sub  ; cudaGetSymbolAddress((void**)&srcs_sub,  g_srcs_sub);
    int* srcs_glob ; cudaGetSymbolAddress((void**)&srcs_glob, g_srcs_glob);
    int* bsum_sub  ; cudaGetSymbolAddress((void**)&bsum_sub,  g_bsum_sub);
    int* bsum_glob ; cudaGetSymbolAddress((void**)&bsum_glob, g_bsum_glob);

    const int T = 256;
    const int NB_sub  = n_sub  / 256;
    const int NB_glob = n_glob / 256;

    // ---- init + counting sort (both graphs) ----
    {
        int span = S * H;
        if (n_glob > span) span = n_glob;
        k_init<<<(span + T - 1) / T, T>>>(n_sub, n_glob, S);
    }
    k_count<<<(E_sub  + T - 1) / T, T>>>(cols_sub,  E_sub,  cnt_sub);
    k_count<<<(E_glob + T - 1) / T, T>>>(cols_glob, E_glob, cnt_glob);
    k_cnt<<<(n_sub + T - 1) / T, T>>>(batch_sub, n_sub);

    k_blocksum<<<NB_sub,  256>>>(cnt_sub,  bsum_sub);
    k_blocksum<<<NB_glob, 256>>>(cnt_glob, bsum_glob);
    k_scan_bsum<<<1, 256>>>(bsum_sub,  NB_sub);
    k_scan_bsum<<<1, 256>>>(bsum_glob, NB_glob);
    k_scan_chunks<<<NB_sub,  256>>>(cnt_sub,  bsum_sub,  off_sub,  cur_sub,  dinv_sub,  n_sub);
    k_scan_chunks<<<NB_glob, 256>>>(cnt_glob, bsum_glob, off_glob, cur_glob, dinv_glob, n_glob);
    k_bucket<<<(E_sub  + T - 1) / T, T>>>(rows_sub,  cols_sub,  cur_sub,  srcs_sub,  E_sub);
    k_bucket<<<(E_glob + T - 1) / T, T>>>(rows_glob, cols_glob, cur_glob, srcs_glob, E_glob);

    // ---- sub conv: GEMM then gather(+bias+relu+pool) ----
    k_sgemm<<<dim3(2, n_sub / 128), 256>>>(x_sub, W_sub, h_sub, n_sub);
    k_gather_sub<<<(n_sub * 32 + 255) / 256, 256>>>(h_sub, b_sub, batch_sub, n_sub);

    // ---- pooled mean -> small GEMM -> inject into h_glob ----
    k_poolmean<<<(S * H + T - 1) / T, T>>>(S);

    // h_glob = x_glob @ W_glob  (independent; scheduled here, before inject)
    k_sgemm<<<dim3(2, n_glob / 128), 256>>>(x_glob, W_glob, h_glob, n_glob);

    k_sgemm<<<dim3(2, S / 128), 256>>>(pmean, W_glob, pooledW, S);
    k_inject<<<(S * 64 + T - 1) / T, T>>>(sub_index, S);

    // ---- glob conv gather(+bias+relu+global reduce) ----
    k_gather_glob<<<(n_glob * 32 + 511) / 512, 512>>>(h_glob, b_glob, n_glob);

    // ---- FC ----
    k_final<<<1, H>>>(fc_W, fc_b, out, 1.0f / (float)n_glob);
}

// round 3
// speedup vs baseline: 1.9466x; 1.4942x over previous
#include <cuda_runtime.h>
#include <cstdint>

// ---------------------------------------------------------------------------
// GCNWithSubgraphs, gather-based + tf32 tensor-core GEMMs.
// H = 256 throughout.
// ---------------------------------------------------------------------------

#define H 256
#define MAX_NSUB  32768
#define MAX_NGLOB 65536
#define MAX_S     1024
#define MAX_ESUB  262144
#define MAX_EGLOB 1048576

__device__ float g_h_sub[MAX_NSUB * H];     // x_sub @ W_sub
__device__ float g_h_glob[MAX_NGLOB * H];   // x_glob @ W_glob (+ injection)
__device__ float g_pool_sum[MAX_S * H];     // holds per-subgraph MEAN (scaled in gather)
__device__ float g_pooledW[MAX_S * H];      // pool_mean @ W_glob
__device__ float g_pool_cnt[MAX_S];
__device__ float g_gemb[H];

__device__ int   g_cnt_sub[MAX_NSUB];
__device__ int   g_off_sub[MAX_NSUB + 1];
__device__ int   g_cur_sub[MAX_NSUB];
__device__ float g_dinv_sub[MAX_NSUB];
__device__ int   g_srcs_sub[MAX_ESUB];

__device__ int   g_cnt_glob[MAX_NGLOB];
__device__ int   g_off_glob[MAX_NGLOB + 1];
__device__ int   g_cur_glob[MAX_NGLOB];
__device__ float g_dinv_glob[MAX_NGLOB];
__device__ int   g_srcs_glob[MAX_EGLOB];

__device__ int   g_bsum_sub[256];
__device__ int   g_bsum_glob[256];

// vectorized fp32 reduction (sm_90+)
__device__ __forceinline__ void red_add_v4(float* a, float4 v) {
    asm volatile("red.global.add.v4.f32 [%0], {%1,%2,%3,%4};"
                 :: "l"(a), "f"(v.x), "f"(v.y), "f"(v.z), "f"(v.w)
                 : "memory");
}

__device__ __forceinline__ uint32_t f2tf32(float f) {
    uint32_t r;
    asm("cvt.rna.tf32.f32 %0, %1;" : "=r"(r) : "f"(f));
    return r;
}

__device__ __forceinline__ float4 f4_fma(float4 a, float s, float4 acc) {
    acc.x = fmaf(a.x, s, acc.x); acc.y = fmaf(a.y, s, acc.y);
    acc.z = fmaf(a.z, s, acc.z); acc.w = fmaf(a.w, s, acc.w);
    return acc;
}
__device__ __forceinline__ float4 f4_relu_addb(float4 a, float4 b) {
    float4 r;
    r.x = fmaxf(a.x + b.x, 0.0f); r.y = fmaxf(a.y + b.y, 0.0f);
    r.z = fmaxf(a.z + b.z, 0.0f); r.w = fmaxf(a.w + b.w, 0.0f);
    return r;
}

// ---------------------------------------------------------------------------
// init + counting sort
// ---------------------------------------------------------------------------
__global__ void k_init(int n_sub, int n_glob, int s) {
    int i = blockIdx.x * blockDim.x + threadIdx.x;
    if (i < n_sub)  g_cnt_sub[i]  = 0;
    if (i < n_glob) g_cnt_glob[i] = 0;
    if (i < s * H)  g_pool_sum[i] = 0.0f;
    if (i < s)      g_pool_cnt[i] = 0.0f;
    if (i < H)      g_gemb[i]     = 0.0f;
}

__global__ void k_count(const int* __restrict__ col, int E, int* __restrict__ cnt) {
    int i = blockIdx.x * blockDim.x + threadIdx.x;
    if (i < E) atomicAdd(&cnt[col[i]], 1);
}

__global__ void k_blocksum(const int* __restrict__ cnt, int* __restrict__ bsum) {
    __shared__ int sh[256];
    int t = threadIdx.x;
    sh[t] = cnt[blockIdx.x * 256 + t];
    __syncthreads();
    #pragma unroll
    for (int s = 128; s > 0; s >>= 1) {
        if (t < s) sh[t] += sh[t + s];
        __syncthreads();
    }
    if (t == 0) bsum[blockIdx.x] = sh[0];
}

__global__ void k_scan_bsum(int* __restrict__ bsum, int NB) {
    __shared__ int sh[256];
    int t = threadIdx.x;
    sh[t] = (t < NB) ? bsum[t] : 0;
    __syncthreads();
    #pragma unroll
    for (int d = 1; d < 256; d <<= 1) {
        int v = (t >= d) ? sh[t - d] : 0;
        __syncthreads();
        sh[t] += v;
        __syncthreads();
    }
    int ex = (t == 0) ? 0 : sh[t - 1];
    if (t < NB) bsum[t] = ex;
}

__global__ void k_scan_chunks(const int* __restrict__ cnt, const int* __restrict__ bsum,
                              int* __restrict__ off, int* __restrict__ cur,
                              float* __restrict__ dinv, int N) {
    __shared__ int sh[256];
    int t = threadIdx.x;
    int i = blockIdx.x * 256 + t;
    int c = cnt[i];
    sh[t] = c;
    __syncthreads();
    #pragma unroll
    for (int d = 1; d < 256; d <<= 1) {
        int v = (t >= d) ? sh[t - d] : 0;
        __syncthreads();
        sh[t] += v;
        __syncthreads();
    }
    int excl = sh[t] - c + bsum[blockIdx.x];
    off[i] = excl;
    cur[i] = excl;
    dinv[i] = rsqrtf((float)(c + 1));
    if (i == N - 1) off[N] = excl + c;
}

__global__ void k_bucket(const int* __restrict__ rows, const int* __restrict__ cols,
                         int* __restrict__ cur, int* __restrict__ srcs, int E) {
    int e = blockIdx.x * blockDim.x + threadIdx.x;
    if (e < E) {
        int c = cols[e];
        int p = atomicAdd(&cur[c], 1);
        srcs[p] = rows[e];
    }
}

// ---------------------------------------------------------------------------
// tf32 MMA GEMM: C[M,256] = A[M,256] @ B[256,256], row-major, M % 128 == 0.
// Block 128x128 (grid.x = 2 column tiles), 256 threads = 8 warps (4x2),
// warp tile 32x64, mma.m16n8k8.tf32.
// ---------------------------------------------------------------------------
#define ASTRIDE 136   // 136 % 32 == 8 -> frag loads conflict-free
#define BSTRIDE 136

__global__ __launch_bounds__(256) void k_mma(const float* __restrict__ A,
                                             const float* __restrict__ B,
                                             float* __restrict__ C, int M) {
    __shared__ uint32_t As[32 * ASTRIDE];   // [k][m]
    __shared__ uint32_t Bs[32 * BSTRIDE];   // [k][n]

    const int tid  = threadIdx.x;
    const int lane = tid & 31;
    const int wid  = tid >> 5;
    const int warpM = wid >> 1;          // 0..3
    const int warpN = wid & 1;           // 0..1
    const int g  = lane >> 2;            // groupID 0..7
    const int tg = lane & 3;             // thread-in-group 0..3
    const int mb = warpM * 32;
    const int nb = warpN * 64;

    const int bc = blockIdx.x;           // column tile (0..1)
    const int br = blockIdx.y;           // row tile

    const float* Ab = A + (size_t)br * 128 * H;
    const float* Bb = B + bc * 128;

    // A load indices: thread covers row ar, 16 k's starting at ac
    const int ar = tid >> 1;
    const int ac = (tid & 1) * 16;
    // B load indices: thread covers k-row bk, 16 n's starting at bn
    const int bk = tid >> 3;
    const int bn = (tid & 7) * 16;

    float c[2][8][4];
    #pragma unroll
    for (int mt = 0; mt < 2; mt++)
        #pragma unroll
        for (int nt = 0; nt < 8; nt++)
            #pragma unroll
            for (int i = 0; i < 4; i++) c[mt][nt][i] = 0.0f;

    for (int k0 = 0; k0 < H; k0 += 32) {
        // load A tile (transpose to [k][m], convert to tf32)
        #pragma unroll
        for (int i = 0; i < 4; i++) {
            float4 v = *(const float4*)(Ab + ar * H + k0 + ac + 4 * i);
            int k = ac + 4 * i;
            As[(k + 0) * ASTRIDE + ar] = f2tf32(v.x);
            As[(k + 1) * ASTRIDE + ar] = f2tf32(v.y);
            As[(k + 2) * ASTRIDE + ar] = f2tf32(v.z);
            As[(k + 3) * ASTRIDE + ar] = f2tf32(v.w);
        }
        // load B tile ([k][n], convert)
        #pragma unroll
        for (int i = 0; i < 4; i++) {
            float4 v = *(const float4*)(Bb + (size_t)(k0 + bk) * H + bn + 4 * i);
            uint32_t* dst = &Bs[bk * BSTRIDE + bn + 4 * i];
            dst[0] = f2tf32(v.x); dst[1] = f2tf32(v.y);
            dst[2] = f2tf32(v.z); dst[3] = f2tf32(v.w);
        }
        __syncthreads();

        #pragma unroll
        for (int kk = 0; kk < 4; kk++) {
            const int k = kk * 8;
            uint32_t a[2][4];
            #pragma unroll
            for (int mt = 0; mt < 2; mt++) {
                int m = mb + mt * 16 + g;
                a[mt][0] = As[(k + tg)     * ASTRIDE + m];
                a[mt][1] = As[(k + tg)     * ASTRIDE + m + 8];
                a[mt][2] = As[(k + tg + 4) * ASTRIDE + m];
                a[mt][3] = As[(k + tg + 4) * ASTRIDE + m + 8];
            }
            #pragma unroll
            for (int nt = 0; nt < 8; nt++) {
                int n = nb + nt * 8 + g;
                uint32_t b0 = Bs[(k + tg)     * BSTRIDE + n];
                uint32_t b1 = Bs[(k + tg + 4) * BSTRIDE + n];
                #pragma unroll
                for (int mt = 0; mt < 2; mt++) {
                    asm volatile(
                        "mma.sync.aligned.m16n8k8.row.col.f32.tf32.tf32.f32 "
                        "{%0,%1,%2,%3}, {%4,%5,%6,%7}, {%8,%9}, {%0,%1,%2,%3};"
                        : "+f"(c[mt][nt][0]), "+f"(c[mt][nt][1]),
                          "+f"(c[mt][nt][2]), "+f"(c[mt][nt][3])
                        : "r"(a[mt][0]), "r"(a[mt][1]), "r"(a[mt][2]), "r"(a[mt][3]),
                          "r"(b0), "r"(b1));
                }
            }
        }
        __syncthreads();
    }

    // writeback
    float* Cb = C + (size_t)br * 128 * H + bc * 128;
    #pragma unroll
    for (int mt = 0; mt < 2; mt++) {
        int r0 = mb + mt * 16 + g;
        #pragma unroll
        for (int nt = 0; nt < 8; nt++) {
            int col = nb + nt * 8 + 2 * tg;
            *(float2*)(Cb + (size_t)r0 * H + col)       = make_float2(c[mt][nt][0], c[mt][nt][1]);
            *(float2*)(Cb + (size_t)(r0 + 8) * H + col) = make_float2(c[mt][nt][2], c[mt][nt][3]);
        }
    }
}

// ---------------------------------------------------------------------------
// gather core: warp per node
// ---------------------------------------------------------------------------
__device__ __forceinline__ void gather_node(const float4* __restrict__ hp,
                                            const int* __restrict__ off,
                                            const int* __restrict__ srcs,
                                            const float* __restrict__ dinv,
                                            int n, int lane,
                                            float4& a0, float4& a1) {
    int base = off[n];
    int end  = off[n + 1];
    float di = dinv[n];
    float sn = di * di;
    const float4* hn = hp + (size_t)n * 64;
    a0 = hn[lane];      a1 = hn[lane + 32];
    a0.x *= sn; a0.y *= sn; a0.z *= sn; a0.w *= sn;
    a1.x *= sn; a1.y *= sn; a1.z *= sn; a1.w *= sn;

    int e = base;
    int r = (e < end) ? __ldg(&srcs[e]) : 0;
    for (; e < end; e++) {
        int rn = (e + 1 < end) ? __ldg(&srcs[e + 1]) : 0;
        float nm = di * __ldg(&dinv[r]);
        const float4* hr = hp + (size_t)r * 64;
        float4 v0 = __ldg(hr + lane);
        float4 v1 = __ldg(hr + lane + 32);
        a0 = f4_fma(v0, nm, a0);
        a1 = f4_fma(v1, nm, a1);
        r = rn;
    }
}

// sub: + bias, relu, scale by 1/cnt, pool-scatter (sum becomes mean directly)
__global__ __launch_bounds__(256) void k_gather_sub(const float* __restrict__ h,
                                                    const float* __restrict__ bias,
                                                    const int* __restrict__ batch, int N) {
    int warp = (blockIdx.x * blockDim.x + threadIdx.x) >> 5;
    int lane = threadIdx.x & 31;
    if (warp >= N) return;
    float4 a0, a1;
    gather_node((const float4*)h, g_off_sub, g_srcs_sub, g_dinv_sub, warp, lane, a0, a1);
    const float4* b4 = (const float4*)bias;
    a0 = f4_relu_addb(a0, __ldg(b4 + lane));
    a1 = f4_relu_addb(a1, __ldg(b4 + lane + 32));
    int s = batch[warp];
    float ic = 1.0f / fmaxf(g_pool_cnt[s], 1.0f);
    a0.x *= ic; a0.y *= ic; a0.z *= ic; a0.w *= ic;
    a1.x *= ic; a1.y *= ic; a1.z *= ic; a1.w *= ic;
    float* ps = g_pool_sum + (size_t)s * H;
    red_add_v4(ps + 4 * lane, a0);
    red_add_v4(ps + 4 * (lane + 32), a1);
}

// glob: + bias, relu, block-shared reduce -> global atomics
__global__ __launch_bounds__(512) void k_gather_glob(const float* __restrict__ h,
                                                     const float* __restrict__ bias, int N) {
    __shared__ float sh[H];
    int t = threadIdx.x;
    if (t < H) sh[t] = 0.0f;
    __syncthreads();

    int warp = (blockIdx.x * blockDim.x + t) >> 5;
    int lane = t & 31;
    if (warp < N) {
        float4 a0, a1;
        gather_node((const float4*)h, g_off_glob, g_srcs_glob, g_dinv_glob, warp, lane, a0, a1);
        const float4* b4 = (const float4*)bias;
        a0 = f4_relu_addb(a0, __ldg(b4 + lane));
        a1 = f4_relu_addb(a1, __ldg(b4 + lane + 32));
        int c0 = 4 * lane, c1 = 4 * (lane + 32);
        atomicAdd(&sh[c0 + 0], a0.x); atomicAdd(&sh[c0 + 1], a0.y);
        atomicAdd(&sh[c0 + 2], a0.z); atomicAdd(&sh[c0 + 3], a0.w);
        atomicAdd(&sh[c1 + 0], a1.x); atomicAdd(&sh[c1 + 1], a1.y);
        atomicAdd(&sh[c1 + 2], a1.z); atomicAdd(&sh[c1 + 3], a1.w);
    }
    __syncthreads();
    if (t < H) atomicAdd(&g_gemb[t], sh[t]);
}

__global__ void k_cnt(const int* __restrict__ batch, int n) {
    int i = blockIdx.x * blockDim.x + threadIdx.x;
    if (i < n) atomicAdd(&g_pool_cnt[batch[i]], 1.0f);
}

// h_glob[sub_index[g]] += pooledW[g]
__global__ void k_inject(const int* __restrict__ sub_index, int s) {
    int i = blockIdx.x * blockDim.x + threadIdx.x;     // float4 index
    if (i < s * 64) {
        int g  = i >> 6;
        int f4 = i & 63;
        int node = sub_index[g];
        float4 v = ((const float4*)g_pooledW)[i];
        red_add_v4(&g_h_glob[(size_t)node * H + 4 * f4], v);
    }
}

// out[j] = (gemb/n_glob) . fc_W[j,:] + fc_b[j]
__global__ void k_final(const float* __restrict__ fc_W, const float* __restrict__ fc_b,
                        float* __restrict__ out, float inv_n) {
    __shared__ float ge[H];
    int t = threadIdx.x;
    ge[t] = g_gemb[t] * inv_n;
    __syncthreads();
    float s = 0.0f;
    #pragma unroll 8
    for (int f = 0; f < H; f++) s += ge[f] * fc_W[t * H + f];
    out[t] = s + fc_b[t];
}

// ---------------------------------------------------------------------------
extern "C" void kernel_launch(void* const* d_in, const int* in_sizes, int n_in,
                              void* d_out, int out_size) {
    const float* x_sub      = (const float*)d_in[0];
    const int*   ei_sub     = (const int*)  d_in[1];
    const int*   batch_sub  = (const int*)  d_in[2];
    const int*   sub_index  = (const int*)  d_in[3];
    const float* x_glob     = (const float*)d_in[4];
    const int*   ei_glob    = (const int*)  d_in[5];
    const float* W_sub      = (const float*)d_in[7];
    const float* b_sub      = (const float*)d_in[8];
    const float* W_glob     = (const float*)d_in[9];
    const float* b_glob     = (const float*)d_in[10];
    const float* fc_W       = (const float*)d_in[11];
    const float* fc_b       = (const float*)d_in[12];
    float* out = (float*)d_out;

    const int n_sub  = in_sizes[0] / H;     // 32768
    const int E_sub  = in_sizes[1] / 2;     // 262144
    const int S      = in_sizes[3];         // 1024
    const int n_glob = in_sizes[4] / H;     // 65536
    const int E_glob = in_sizes[5] / 2;     // 1048576

    const int* rows_sub  = ei_sub;
    const int* cols_sub  = ei_sub + E_sub;
    const int* rows_glob = ei_glob;
    const int* cols_glob = ei_glob + E_glob;

    float* h_sub   ; cudaGetSymbolAddress((void**)&h_sub,    g_h_sub);
    float* h_glob  ; cudaGetSymbolAddress((void**)&h_glob,   g_h_glob);
    float* psum    ; cudaGetSymbolAddress((void**)&psum,     g_pool_sum);
    float* pooledW ; cudaGetSymbolAddress((void**)&pooledW,  g_pooledW);
    int* cnt_sub   ; cudaGetSymbolAddress((void**)&cnt_sub,  g_cnt_sub);
    int* cnt_glob  ; cudaGetSymbolAddress((void**)&cnt_glob, g_cnt_glob);
    int* off_sub   ; cudaGetSymbolAddress((void**)&off_sub,  g_off_sub);
    int* off_glob  ; cudaGetSymbolAddress((void**)&off_glob, g_off_glob);
    int* cur_sub   ; cudaGetSymbolAddress((void**)&cur_sub,  g_cur_sub);
    int* cur_glob  ; cudaGetSymbolAddress((void**)&cur_glob, g_cur_glob);
    float* dinv_sub ; cudaGetSymbolAddress((void**)&dinv_sub,  g_dinv_sub);
    float* dinv_glob; cudaGetSymbolAddress((void**)&dinv_glob, g_dinv_glob);
    int* srcs_sub  ; cudaGetSymbolAddress((void**)&srcs_sub,  g_srcs_sub);
    int* srcs_glob ; cudaGetSymbolAddress((void**)&srcs_glob, g_srcs_glob);
    int* bsum_sub  ; cudaGetSymbolAddress((void**)&bsum_sub,  g_bsum_sub);
    int* bsum_glob ; cudaGetSymbolAddress((void**)&bsum_glob, g_bsum_glob);

    const int T = 256;
    const int NB_sub  = n_sub  / 256;
    const int NB_glob = n_glob / 256;

    // ---- init + counting sort ----
    {
        int span = S * H;
        if (n_glob > span) span = n_glob;
        k_init<<<(span + T - 1) / T, T>>>(n_sub, n_glob, S);
    }
    k_count<<<(E_sub  + T - 1) / T, T>>>(cols_sub,  E_sub,  cnt_sub);
    k_count<<<(E_glob + T - 1) / T, T>>>(cols_glob, E_glob, cnt_glob);
    k_cnt<<<(n_sub + T - 1) / T, T>>>(batch_sub, n_sub);

    k_blocksum<<<NB_sub,  256>>>(cnt_sub,  bsum_sub);
    k_blocksum<<<NB_glob, 256>>>(cnt_glob, bsum_glob);
    k_scan_bsum<<<1, 256>>>(bsum_sub,  NB_sub);
    k_scan_bsum<<<1, 256>>>(bsum_glob, NB_glob);
    k_scan_chunks<<<NB_sub,  256>>>(cnt_sub,  bsum_sub,  off_sub,  cur_sub,  dinv_sub,  n_sub);
    k_scan_chunks<<<NB_glob, 256>>>(cnt_glob, bsum_glob, off_glob, cur_glob, dinv_glob, n_glob);
    k_bucket<<<(E_sub  + T - 1) / T, T>>>(rows_sub,  cols_sub,  cur_sub,  srcs_sub,  E_sub);
    k_bucket<<<(E_glob + T - 1) / T, T>>>(rows_glob, cols_glob, cur_glob, srcs_glob, E_glob);

    // ---- sub conv: tf32 GEMM then gather(+bias+relu+mean-pool) ----
    k_mma<<<dim3(2, n_sub / 128), 256>>>(x_sub, W_sub, h_sub, n_sub);
    k_gather_sub<<<(n_sub * 32 + 255) / 256, 256>>>(h_sub, b_sub, batch_sub, n_sub);

    // h_glob = x_glob @ W_glob
    k_mma<<<dim3(2, n_glob / 128), 256>>>(x_glob, W_glob, h_glob, n_glob);

    // pooledW = pool_mean @ W_glob; inject rows
    k_mma<<<dim3(2, S / 128), 256>>>(psum, W_glob, pooledW, S);
    k_inject<<<(S * 64 + T - 1) / T, T>>>(sub_index, S);

    // ---- glob conv gather(+bias+relu+global reduce) ----
    k_gather_glob<<<(n_glob * 32 + 511) / 512, 512>>>(h_glob, b_glob, n_glob);

    // ---- FC ----
    k_final<<<1, H>>>(fc_W, fc_b, out, 1.0f / (float)n_glob);
}